// round 1
// baseline (speedup 1.0000x reference)
#include <cuda_runtime.h>
#include <math.h>
#include <stdint.h>

#define N_TOK 16384
#define DIM   2048
#define NEXP  64
#define KSEL  9
#define EPS_C 0.01f
// 1 / (SIGMA * sqrt(2)) with SIGMA = 1/64
#define INV_SIG_SQRT2 45.254833995939045f

#define BM 128
#define BK 32
#define XS_STRIDE 132   // padded, multiple of 4 for aligned float4 LDS
#define ACC_STRIDE 129  // odd stride -> conflict-free row scans

// smem budget (floats):
//   GEMM phase : x_sT[32][132] (4224) + w_s[32][128] (4096)          = 8320
//   Epilogue   : acc_s[128][129] (16512) + imp_s[64] + load_s[64]    = 16640
#define SMEM_FLOATS 16640
#define SMEM_BYTES  (SMEM_FLOATS * 4)

__device__ __forceinline__ unsigned long long pack_dup(float a) {
    unsigned long long r;
    unsigned ai = __float_as_uint(a);
    asm("mov.b64 %0, {%1, %1};" : "=l"(r) : "r"(ai));
    return r;
}

extern "C" __global__ void __launch_bounds__(256, 1)
router_kernel(const float* __restrict__ x,  const float* __restrict__ Wr,
              const float* __restrict__ br, const float* __restrict__ Wn,
              const float* __restrict__ bn, const float* __restrict__ neps,
              const float* __restrict__ gum, float* __restrict__ out)
{
    extern __shared__ float smem[];
    float* x_sT = smem;                      // [BK][XS_STRIDE]
    float* w_s  = smem + BK * XS_STRIDE;     // [BK][128]  (cols 0-63 Wr, 64-127 Wn)
    float* acc_s  = smem;                    // epilogue overlay [128][ACC_STRIDE]
    float* imp_s  = smem + BM * ACC_STRIDE;  // [64]
    float* load_s = imp_s + 64;              // [64]

    const int tid = threadIdx.x;
    const int ty = tid >> 4, tx = tid & 15;
    const int row0 = blockIdx.x * BM;

    // 8 rows x 8 cols per thread; cols kept as 4 packed f32x2 pairs
    unsigned long long acc[8][4];
    #pragma unroll
    for (int i = 0; i < 8; i++)
        #pragma unroll
        for (int j = 0; j < 4; j++) acc[i][j] = 0ULL;

    for (int kb = 0; kb < DIM / BK; kb++) {
        const int k0 = kb * BK;
        // ---- load x tile, transposed into x_sT[k][row] ----
        #pragma unroll
        for (int it = 0; it < 4; it++) {
            int e = it * 1024 + tid * 4;
            int r = e >> 5, c = e & 31;
            float4 v = *(const float4*)(x + (size_t)(row0 + r) * DIM + k0 + c);
            x_sT[(c + 0) * XS_STRIDE + r] = v.x;
            x_sT[(c + 1) * XS_STRIDE + r] = v.y;
            x_sT[(c + 2) * XS_STRIDE + r] = v.z;
            x_sT[(c + 3) * XS_STRIDE + r] = v.w;
        }
        // ---- load weight tile: [k][0:64]=Wr, [k][64:128]=Wn ----
        #pragma unroll
        for (int it = 0; it < 4; it++) {
            int e = it * 1024 + tid * 4;
            int r = e >> 7, c = e & 127;
            const float* src = (c < 64) ? (Wr + (size_t)(k0 + r) * NEXP + c)
                                        : (Wn + (size_t)(k0 + r) * NEXP + (c - 64));
            *(float4*)(w_s + r * 128 + c) = *(const float4*)src;
        }
        __syncthreads();

        #pragma unroll
        for (int kk = 0; kk < BK; kk++) {
            float4 a0 = *(float4*)(x_sT + kk * XS_STRIDE + ty * 8);
            float4 a1 = *(float4*)(x_sT + kk * XS_STRIDE + ty * 8 + 4);
            ulonglong2 b0 = *(ulonglong2*)(w_s + kk * 128 + tx * 8);
            ulonglong2 b1 = *(ulonglong2*)(w_s + kk * 128 + tx * 8 + 4);
            float av[8] = {a0.x, a0.y, a0.z, a0.w, a1.x, a1.y, a1.z, a1.w};
            unsigned long long bp[4] = {b0.x, b0.y, b1.x, b1.y};
            #pragma unroll
            for (int i = 0; i < 8; i++) {
                unsigned long long a2 = pack_dup(av[i]);
                #pragma unroll
                for (int j = 0; j < 4; j++) {
                    asm("fma.rn.f32x2 %0, %1, %2, %0;"
                        : "+l"(acc[i][j]) : "l"(a2), "l"(bp[j]));
                }
            }
        }
        __syncthreads();
    }

    // ---- dump accumulators into smem (overlay), init reduction bins ----
    #pragma unroll
    for (int i = 0; i < 8; i++) {
        int rr = ty * 8 + i;
        #pragma unroll
        for (int j = 0; j < 4; j++) {
            float lo = __uint_as_float((unsigned)(acc[i][j] & 0xffffffffULL));
            float hi = __uint_as_float((unsigned)(acc[i][j] >> 32));
            acc_s[rr * ACC_STRIDE + tx * 8 + 2 * j]     = lo;
            acc_s[rr * ACC_STRIDE + tx * 8 + 2 * j + 1] = hi;
        }
    }
    if (tid < 64) { imp_s[tid] = 0.f; load_s[tid] = 0.f; }
    __syncthreads();

    // ---- per-row epilogue: one thread per row (threads 0..127) ----
    if (tid < BM) {
        const int lr = tid;
        const int grow = row0 + lr;
        float* rowraw = acc_s + lr * ACC_STRIDE;   // cols 0..63  : raw logits
        float* rowns  = rowraw + 64;               // cols 64..127: pre -> noisy
        const float* eps_row = neps + (size_t)grow * NEXP;
        const float* g_row   = gum  + (size_t)grow * NEXP;

        float stdv[NEXP];
        #pragma unroll
        for (int e = 0; e < NEXP; e++) {
            float raw = rowraw[e] + br[e];
            rowraw[e] = raw;
            float pre = rowns[e] + bn[e];
            // softplus = max(x,0) + log1p(exp(-|x|))  (matches jax.nn.softplus)
            float sd = fmaxf(pre, 0.f) + log1pf(expf(-fabsf(pre))) + EPS_C;
            stdv[e] = sd;
            rowns[e] = fmaf(eps_row[e], sd, raw);   // noisy logits
        }

        // top-9 of noisy: threshold (9th largest) + hard mask
        unsigned long long taken = 0ULL;
        float thr = 0.f;
        for (int t = 0; t < KSEL; t++) {
            float m = -INFINITY; int mi = 0;
            for (int e = 0; e < NEXP; e++) {
                float v = rowns[e];
                if (!((taken >> e) & 1ULL) && v > m) { m = v; mi = e; }
            }
            taken |= (1ULL << mi);
            thr = m;
        }

        // softmax maxes: noisy (m1), noisy+gumbel (m2), raw (m3)
        float m1 = -INFINITY, m2 = -INFINITY, m3 = -INFINITY;
        #pragma unroll
        for (int e = 0; e < NEXP; e++) {
            float nz = rowns[e];
            m1 = fmaxf(m1, nz);
            m2 = fmaxf(m2, nz + g_row[e]);
            m3 = fmaxf(m3, rowraw[e]);
        }
        float s1 = 0.f, s2 = 0.f, s3 = 0.f;
        #pragma unroll
        for (int e = 0; e < NEXP; e++) {
            float nz = rowns[e];
            s1 += expf(nz - m1);
            s2 += expf(nz + g_row[e] - m2);
            s3 += expf(rowraw[e] - m3);
        }
        float i1 = 1.f / s1, i2 = 1.f / s2, i3 = 1.f / s3;

        float* om  = out + (size_t)grow * NEXP;
        float* orp = out + (size_t)N_TOK * NEXP + (size_t)grow * NEXP;
        #pragma unroll
        for (int e = 0; e < NEXP; e++) {
            float nz  = rowns[e];
            float raw = rowraw[e];
            float ms  = expf(nz + g_row[e] - m2) * i2;         // mask_soft
            float hard = ((taken >> e) & 1ULL) ? 1.f : 0.f;
            om[e]  = (hard - ms) + ms;                          // expert_mask
            orp[e] = expf(nz - m1) * i1;                        // route_prob
            float imp = expf(raw - m3) * i3;                    // importance term
            float z = (thr - raw) / stdv[e];
            float ld = 0.5f * (1.f - erff(z * INV_SIG_SQRT2));  // 1 - cdf

            // reduce across the 128 row-threads of this block (4 full warps)
            #pragma unroll
            for (int o = 16; o; o >>= 1) {
                imp += __shfl_xor_sync(0xffffffffu, imp, o);
                ld  += __shfl_xor_sync(0xffffffffu, ld,  o);
            }
            if ((tid & 31) == 0) {
                atomicAdd(&imp_s[e], imp);
                atomicAdd(&load_s[e], ld);
            }
        }
    }
    __syncthreads();
    if (tid < 64) {
        atomicAdd(out + 2 * (size_t)N_TOK * NEXP + tid,        imp_s[tid]);
        atomicAdd(out + 2 * (size_t)N_TOK * NEXP + NEXP + tid, load_s[tid]);
    }
}

extern "C" void kernel_launch(void* const* d_in, const int* in_sizes, int n_in,
                              void* d_out, int out_size)
{
    const float* x    = (const float*)d_in[0];
    const float* Wr   = (const float*)d_in[1];
    const float* br   = (const float*)d_in[2];
    const float* Wn   = (const float*)d_in[3];
    const float* bn   = (const float*)d_in[4];
    const float* neps = (const float*)d_in[5];
    const float* gum  = (const float*)d_in[6];
    float* out = (float*)d_out;

    cudaFuncSetAttribute(router_kernel,
                         cudaFuncAttributeMaxDynamicSharedMemorySize, SMEM_BYTES);

    // importance + load are accumulated via atomics -> zero-init (d_out is poisoned)
    cudaMemsetAsync(out + 2 * (size_t)N_TOK * NEXP, 0, 2 * NEXP * sizeof(float));

    router_kernel<<<N_TOK / BM, 256, SMEM_BYTES>>>(x, Wr, br, Wn, bn, neps, gum, out);
}